// round 8
// baseline (speedup 1.0000x reference)
#include <cuda_runtime.h>

#define NPTS   1024
#define BTOT   32
#define RESV   48
#define SPIX   (RESV*RESV)
#define TILES  8
#define TROWS  6

#define NSUBG  24            // global 2-row sub-strips
#define NCB    8             // col bins (6 cols each)
#define NBINB  (NSUBG*NCB)   // 192 bins per batch
#define CAPB   384           // per-bin capacity (worst-case central bin ~270)
#define BSTR   392           // bin stride in float4 (CAPB-1+7 < BSTR)

// global scratch (no allocations allowed): ~38.5 MB bins + counts
__device__ float4 g_bins[(size_t)BTOT * NBINB * BSTR];
__device__ int    g_bcnt[BTOT * NBINB];

// exact membership conditions (identical in ballot + scatter)
__device__ __forceinline__ bool sub_cond(float X, int s) {
    // sub-strip s covers rows 2s, 2s+1; reachable iff X in (2s-2, 2s+3)
    return (X > (float)(2 * s) - 2.0f) && (X < (float)(2 * s) + 3.0f);
}
__device__ __forceinline__ bool col_cond(float Y, int c) {
    return (Y > (float)(TROWS * c) - 2.0f) && (Y < (float)(TROWS * c + TROWS - 1) + 2.0f);
}

// ---------------------------------------------------------------------------
// Kernel 1: 32 blocks x 1024 threads, 1 point/thread.
// Projection + top-2 + minmax + normalize + ordered scatter into 192 bins.
// ---------------------------------------------------------------------------
__global__ void __launch_bounds__(1024)
prep_kernel(const float* __restrict__ xyz,
            const float* __restrict__ feats,
            const float* __restrict__ theta,
            const float* __restrict__ phi)
{
    __shared__ float    red[32 * 4];
    __shared__ unsigned sbalS[32][NSUBG];   // [warp][substrip]
    __shared__ unsigned sbalC[32][NCB];     // [warp][colbin]
    __shared__ int      wbase[NBINB][32];   // exclusive base per bin per warp

    int b = blockIdx.x;
    int k = b >> 2, m = b & 3;
    int tid = threadIdx.x, lane = tid & 31, wid = tid >> 5;

    float th = theta[m], ph = phi[m];
    float st = sinf(th), ct = cosf(th);
    float sp = sinf(ph), cp = cosf(ph);
    float U0 = -st, U1 = ct;
    float V0 = ct * sp, V1 = st * sp, V2 = cp;
    float cx = ct * cp, cy = st * cp, cz = sp;

    int g = k * NPTS + tid;
    float x = xyz[3 * g + 0];
    float y = xyz[3 * g + 1];
    float z = xyz[3 * g + 2];
    float dx = x - cx, dy = y - cy, dz = z - cz;
    float c0 = dx * U0 + dy * U1;
    float c1 = dx * V0 + dy * V1 + dz * V2;

    // top-2 of 20 (ascending last two of sort: [second, max])
    const float4* fr = (const float4*)(feats + (size_t)g * 20);
    float t1 = -1e30f, t2 = -1e30f;
#pragma unroll
    for (int q = 0; q < 5; q++) {
        float4 v = fr[q];
        float f;
        f = v.x; if (f > t1) { t2 = t1; t1 = f; } else if (f > t2) t2 = f;
        f = v.y; if (f > t1) { t2 = t1; t1 = f; } else if (f > t2) t2 = f;
        f = v.z; if (f > t1) { t2 = t1; t1 = f; } else if (f > t2) t2 = f;
        f = v.w; if (f > t1) { t2 = t1; t1 = f; } else if (f > t2) t2 = f;
    }

    // block minmax (order-invariant, exact)
    float mn0 = c0, mx0 = c0, mn1 = c1, mx1 = c1;
#pragma unroll
    for (int o = 16; o > 0; o >>= 1) {
        mn0 = fminf(mn0, __shfl_xor_sync(0xffffffffu, mn0, o));
        mx0 = fmaxf(mx0, __shfl_xor_sync(0xffffffffu, mx0, o));
        mn1 = fminf(mn1, __shfl_xor_sync(0xffffffffu, mn1, o));
        mx1 = fmaxf(mx1, __shfl_xor_sync(0xffffffffu, mx1, o));
    }
    if (lane == 0) {
        red[wid] = mn0; red[32 + wid] = mx0;
        red[64 + wid] = mn1; red[96 + wid] = mx1;
    }
    __syncthreads();
    mn0 = red[0]; mx0 = red[32]; mn1 = red[64]; mx1 = red[96];
#pragma unroll
    for (int w = 1; w < 32; w++) {
        mn0 = fminf(mn0, red[w]);      mx0 = fmaxf(mx0, red[32 + w]);
        mn1 = fminf(mn1, red[64 + w]); mx1 = fmaxf(mx1, red[96 + w]);
    }
    float ctr0 = (mx0 + mn0) * 0.5f;
    float ctr1 = (mx1 + mn1) * 0.5f;
    float sc0  = fmaxf(mx0 - mn0, 1e-5f) * 0.5f;
    float sc1  = fmaxf(mx1 - mn1, 1e-5f) * 0.5f;

    float X = (__fdiv_rn(c0 - ctr0, sc0) + 1.0f) * 19.2f + 4.8f;
    float Y = (__fdiv_rn(c1 - ctr1, sc1) + 1.0f) * 19.2f + 4.8f;

    // factored ballots: 24 substrip + 8 col per warp (index-ordered lanes)
#pragma unroll
    for (int s = 0; s < NSUBG; s++) {
        unsigned ba = __ballot_sync(0xffffffffu, sub_cond(X, s));
        if (lane == 0) sbalS[wid][s] = ba;
    }
#pragma unroll
    for (int c = 0; c < NCB; c++) {
        unsigned ba = __ballot_sync(0xffffffffu, col_cond(Y, c));
        if (lane == 0) sbalC[wid][c] = ba;
    }
    __syncthreads();

    // 192 bin scans: warp w handles bins 6w..6w+5; lane = source warp
#pragma unroll
    for (int e = 0; e < 6; e++) {
        int bin = wid * 6 + e;
        int s = bin >> 3, c = bin & 7;
        int v = __popc(sbalS[lane][s] & sbalC[lane][c]);
        int incl = v;
#pragma unroll
        for (int o = 1; o < 32; o <<= 1) {
            int n = __shfl_up_sync(0xffffffffu, incl, o);
            if (lane >= o) incl += n;
        }
        wbase[bin][lane] = incl - v;
        if (lane == 31) g_bcnt[b * NBINB + bin] = incl;
    }
    __syncthreads();

    // ordered scatter: each point to its (<=9, avg ~3.75) bins
    unsigned lmask = (1u << lane) - 1u;
    float4 rec = make_float4(X, Y, t2, t1);
    int s0 = max(0, (int)floorf((X - 3.0f) * 0.5f));
    int cb0 = max(0, (int)floorf((Y - 7.0f) * (1.0f / 6.0f)));
#pragma unroll
    for (int ds = 0; ds < 4; ds++) {
        int s = s0 + ds;
        if (s >= NSUBG || !sub_cond(X, s)) continue;
        unsigned mS = sbalS[wid][s];
#pragma unroll
        for (int dc = 0; dc < 3; dc++) {
            int c = cb0 + dc;
            if (c >= NCB || !col_cond(Y, c)) continue;
            unsigned ba = mS & sbalC[wid][c];
            int bin = s * NCB + c;
            int idx = wbase[bin][wid] + __popc(ba & lmask);
            if (idx < CAPB)
                g_bins[((size_t)b * NBINB + bin) * BSTR + idx] = rec;
        }
    }
}

// ---------------------------------------------------------------------------
// Kernel 2: grid (8, 32), 288 threads (9 warps). Pure query — no smem,
// no syncthreads. Warp w: substrip sr=w/3 (2 rows), col group w%3 (16 cols).
// ---------------------------------------------------------------------------
__global__ void __launch_bounds__(288)
mask_kernel(float* __restrict__ out)
{
    int t = blockIdx.x, b = blockIdx.y;
    int tid = threadIdx.x, lane = tid & 31, wid = tid >> 5;

    int sr = wid / 3, cg = wid - 3 * sr;
    int r  = lane >> 4, ccol = lane & 15;
    int i  = t * TROWS + 2 * sr + r;
    int j  = 16 * cg + ccol;
    int c  = j / TROWS;
    int sg = t * 3 + sr;
    int bin = sg * NCB + c;

    int tot = min(g_bcnt[b * NBINB + bin], CAPB);
    const float4* bp = g_bins + ((size_t)b * NBINB + bin) * BSTR;

    int pmax = tot;
#pragma unroll
    for (int o = 16; o > 0; o >>= 1)
        pmax = max(pmax, __shfl_xor_sync(0xffffffffu, pmax, o));

    float sx = (float)i, sy = (float)j;
    int nsel = 0;
    float f0 = 0.0f, f1 = 0.0f;

    for (int p0 = 0; p0 < pmax; p0 += 8) {
        // unconditional warp-broadcast loads (full MLP); stay inside bin slot
        float4 q0 = bp[p0 + 0], q1 = bp[p0 + 1], q2 = bp[p0 + 2], q3 = bp[p0 + 3];
        float4 q4 = bp[p0 + 4], q5 = bp[p0 + 5], q6 = bp[p0 + 6], q7 = bp[p0 + 7];
        float d0, d1, d2v, d3, d4, d5, d6, d7;
        { float a = sx - q0.x, bb = sy - q0.y; d0  = fmaf(a, a, bb * bb); }
        { float a = sx - q1.x, bb = sy - q1.y; d1  = fmaf(a, a, bb * bb); }
        { float a = sx - q2.x, bb = sy - q2.y; d2v = fmaf(a, a, bb * bb); }
        { float a = sx - q3.x, bb = sy - q3.y; d3  = fmaf(a, a, bb * bb); }
        { float a = sx - q4.x, bb = sy - q4.y; d4  = fmaf(a, a, bb * bb); }
        { float a = sx - q5.x, bb = sy - q5.y; d5  = fmaf(a, a, bb * bb); }
        { float a = sx - q6.x, bb = sy - q6.y; d6  = fmaf(a, a, bb * bb); }
        { float a = sx - q7.x, bb = sy - q7.y; d7  = fmaf(a, a, bb * bb); }
        // index guard is ALU-side; junk beyond tot predicated off
        if (p0 + 0 < tot && d0  < 4.0f && nsel < 16) { f0 += q0.z; f1 += q0.w; nsel++; }
        if (p0 + 1 < tot && d1  < 4.0f && nsel < 16) { f0 += q1.z; f1 += q1.w; nsel++; }
        if (p0 + 2 < tot && d2v < 4.0f && nsel < 16) { f0 += q2.z; f1 += q2.w; nsel++; }
        if (p0 + 3 < tot && d3  < 4.0f && nsel < 16) { f0 += q3.z; f1 += q3.w; nsel++; }
        if (p0 + 4 < tot && d4  < 4.0f && nsel < 16) { f0 += q4.z; f1 += q4.w; nsel++; }
        if (p0 + 5 < tot && d5  < 4.0f && nsel < 16) { f0 += q5.z; f1 += q5.w; nsel++; }
        if (p0 + 6 < tot && d6  < 4.0f && nsel < 16) { f0 += q6.z; f1 += q6.w; nsel++; }
        if (p0 + 7 < tot && d7  < 4.0f && nsel < 16) { f0 += q7.z; f1 += q7.w; nsel++; }
        // exact early exit: once nsel==16 nothing later can be selected
        if (__all_sync(0xffffffffu, (p0 + 8 >= tot) | (nsel >= 16))) break;
    }

    float occ = fmaxf((float)nsel, 1.0f);
    float a0 = __fdiv_rn(f0, occ);
    float a1 = __fdiv_rn(f1, occ);
    float mxv = fmaxf(a0, a1);
    float e0 = expf(a0 - mxv);
    float e1 = expf(a1 - mxv);
    float s  = e0 + e1;
    float nf0 = __fdiv_rn(e0, s);
    float nf1 = __fdiv_rn(e1, s);
    float v = (nf0 == nf1) ? 0.0f : nf1 * 255.0f;

    int base = (b * 3) * SPIX + i * RESV + j;
    out[base]            = v;
    out[base + SPIX]     = v;
    out[base + 2 * SPIX] = v;
}

extern "C" void kernel_launch(void* const* d_in, const int* in_sizes, int n_in,
                              void* d_out, int out_size)
{
    const float* xyz   = (const float*)d_in[0];
    const float* feats = (const float*)d_in[1];
    const float* theta = (const float*)d_in[n_in - 2];
    const float* phi   = (const float*)d_in[n_in - 1];
    float* out = (float*)d_out;

    prep_kernel<<<BTOT, 1024>>>(xyz, feats, theta, phi);
    mask_kernel<<<dim3(TILES, BTOT), 288>>>(out);
}

// round 9
// speedup vs baseline: 1.1227x; 1.1227x over previous
#include <cuda_runtime.h>

#define NPTS   1024
#define BTOT   32
#define RESV   48
#define SPIX   (RESV*RESV)
#define TILES  8
#define TROWS  6

#define NSUBG  24            // global 2-row sub-strips
#define NCB    8             // col bins (6 cols each)
#define NBINB  (NSUBG*NCB)   // 192 bins per batch
#define CAPB   384           // per-bin capacity
#define BSTR   392           // bin stride in float4

#define NLOC   24            // bins used per mask block (3 substrips x 8 cols)
#define SCAP   2048          // packed smem capacity (float4)
#define SPAD   2560          // allocated (covers pmax overread)

// global scratch (no allocations allowed)
__device__ float4 g_bins[(size_t)BTOT * NBINB * BSTR];
__device__ int    g_bcnt[BTOT * NBINB];

__device__ __forceinline__ bool sub_cond(float X, int s) {
    return (X > (float)(2 * s) - 2.0f) && (X < (float)(2 * s) + 3.0f);
}
__device__ __forceinline__ bool col_cond(float Y, int c) {
    return (Y > (float)(TROWS * c) - 2.0f) && (Y < (float)(TROWS * c + TROWS - 1) + 2.0f);
}

// ---------------------------------------------------------------------------
// Kernel 1: 32 blocks x 1024 threads, 1 point/thread. (unchanged from R8)
// ---------------------------------------------------------------------------
__global__ void __launch_bounds__(1024)
prep_kernel(const float* __restrict__ xyz,
            const float* __restrict__ feats,
            const float* __restrict__ theta,
            const float* __restrict__ phi)
{
    __shared__ float    red[32 * 4];
    __shared__ unsigned sbalS[32][NSUBG];
    __shared__ unsigned sbalC[32][NCB];
    __shared__ int      wbase[NBINB][32];

    int b = blockIdx.x;
    int k = b >> 2, m = b & 3;
    int tid = threadIdx.x, lane = tid & 31, wid = tid >> 5;

    float th = theta[m], ph = phi[m];
    float st = sinf(th), ct = cosf(th);
    float sp = sinf(ph), cp = cosf(ph);
    float U0 = -st, U1 = ct;
    float V0 = ct * sp, V1 = st * sp, V2 = cp;
    float cx = ct * cp, cy = st * cp, cz = sp;

    int g = k * NPTS + tid;
    float x = xyz[3 * g + 0];
    float y = xyz[3 * g + 1];
    float z = xyz[3 * g + 2];
    float dx = x - cx, dy = y - cy, dz = z - cz;
    float c0 = dx * U0 + dy * U1;
    float c1 = dx * V0 + dy * V1 + dz * V2;

    const float4* fr = (const float4*)(feats + (size_t)g * 20);
    float t1 = -1e30f, t2 = -1e30f;
#pragma unroll
    for (int q = 0; q < 5; q++) {
        float4 v = fr[q];
        float f;
        f = v.x; if (f > t1) { t2 = t1; t1 = f; } else if (f > t2) t2 = f;
        f = v.y; if (f > t1) { t2 = t1; t1 = f; } else if (f > t2) t2 = f;
        f = v.z; if (f > t1) { t2 = t1; t1 = f; } else if (f > t2) t2 = f;
        f = v.w; if (f > t1) { t2 = t1; t1 = f; } else if (f > t2) t2 = f;
    }

    float mn0 = c0, mx0 = c0, mn1 = c1, mx1 = c1;
#pragma unroll
    for (int o = 16; o > 0; o >>= 1) {
        mn0 = fminf(mn0, __shfl_xor_sync(0xffffffffu, mn0, o));
        mx0 = fmaxf(mx0, __shfl_xor_sync(0xffffffffu, mx0, o));
        mn1 = fminf(mn1, __shfl_xor_sync(0xffffffffu, mn1, o));
        mx1 = fmaxf(mx1, __shfl_xor_sync(0xffffffffu, mx1, o));
    }
    if (lane == 0) {
        red[wid] = mn0; red[32 + wid] = mx0;
        red[64 + wid] = mn1; red[96 + wid] = mx1;
    }
    __syncthreads();
    mn0 = red[0]; mx0 = red[32]; mn1 = red[64]; mx1 = red[96];
#pragma unroll
    for (int w = 1; w < 32; w++) {
        mn0 = fminf(mn0, red[w]);      mx0 = fmaxf(mx0, red[32 + w]);
        mn1 = fminf(mn1, red[64 + w]); mx1 = fmaxf(mx1, red[96 + w]);
    }
    float ctr0 = (mx0 + mn0) * 0.5f;
    float ctr1 = (mx1 + mn1) * 0.5f;
    float sc0  = fmaxf(mx0 - mn0, 1e-5f) * 0.5f;
    float sc1  = fmaxf(mx1 - mn1, 1e-5f) * 0.5f;

    float X = (__fdiv_rn(c0 - ctr0, sc0) + 1.0f) * 19.2f + 4.8f;
    float Y = (__fdiv_rn(c1 - ctr1, sc1) + 1.0f) * 19.2f + 4.8f;

#pragma unroll
    for (int s = 0; s < NSUBG; s++) {
        unsigned ba = __ballot_sync(0xffffffffu, sub_cond(X, s));
        if (lane == 0) sbalS[wid][s] = ba;
    }
#pragma unroll
    for (int c = 0; c < NCB; c++) {
        unsigned ba = __ballot_sync(0xffffffffu, col_cond(Y, c));
        if (lane == 0) sbalC[wid][c] = ba;
    }
    __syncthreads();

#pragma unroll
    for (int e = 0; e < 6; e++) {
        int bin = wid * 6 + e;
        int s = bin >> 3, c = bin & 7;
        int v = __popc(sbalS[lane][s] & sbalC[lane][c]);
        int incl = v;
#pragma unroll
        for (int o = 1; o < 32; o <<= 1) {
            int n = __shfl_up_sync(0xffffffffu, incl, o);
            if (lane >= o) incl += n;
        }
        wbase[bin][lane] = incl - v;
        if (lane == 31) g_bcnt[b * NBINB + bin] = incl;
    }
    __syncthreads();

    unsigned lmask = (1u << lane) - 1u;
    float4 rec = make_float4(X, Y, t2, t1);
    int s0 = max(0, (int)floorf((X - 3.0f) * 0.5f));
    int cb0 = max(0, (int)floorf((Y - 7.0f) * (1.0f / 6.0f)));
#pragma unroll
    for (int ds = 0; ds < 4; ds++) {
        int s = s0 + ds;
        if (s >= NSUBG || !sub_cond(X, s)) continue;
        unsigned mS = sbalS[wid][s];
#pragma unroll
        for (int dc = 0; dc < 3; dc++) {
            int c = cb0 + dc;
            if (c >= NCB || !col_cond(Y, c)) continue;
            unsigned ba = mS & sbalC[wid][c];
            int bin = s * NCB + c;
            int idx = wbase[bin][wid] + __popc(ba & lmask);
            if (idx < CAPB)
                g_bins[((size_t)b * NBINB + bin) * BSTR + idx] = rec;
        }
    }
}

// ---------------------------------------------------------------------------
// Kernel 2: grid (8, 32), 288 threads (9 warps).
// Bulk-copy the block's 24 bins into packed smem (coalesced), then query.
// ---------------------------------------------------------------------------
__global__ void __launch_bounds__(288)
mask_kernel(float* __restrict__ out)
{
    __shared__ float4 sbin[SPAD];        // 40 KB
    __shared__ int    sbase[NLOC];
    __shared__ int    scnt[NLOC];

    int t = blockIdx.x, b = blockIdx.y;
    int tid = threadIdx.x, lane = tid & 31, wid = tid >> 5;

    // --- counts + packed bases (warp 0); local bin l = s_local*8 + c ---
    if (wid == 0) {
        int cnt = 0;
        if (lane < NLOC) {
            int sg = t * 3 + (lane >> 3);
            cnt = min(g_bcnt[b * NBINB + sg * NCB + (lane & 7)], CAPB);
        }
        int pad8 = (cnt + 7) & ~7;
        int incl = pad8;
#pragma unroll
        for (int o = 1; o < 32; o <<= 1) {
            int n = __shfl_up_sync(0xffffffffu, incl, o);
            if (lane >= o) incl += n;
        }
        int base = incl - pad8;
        if (lane < NLOC) {
            // clamp so packed data fits SCAP (worst realistic total ~1900)
            int avail = max(0, SCAP - base);
            sbase[lane] = base;
            scnt[lane]  = min(cnt, avail);
        }
    }
    __syncthreads();

    // --- coalesced copy: warp w handles local bins w, w+9, w+18 ---
    for (int l = wid; l < NLOC; l += 9) {
        int sg = t * 3 + (l >> 3);
        const float4* src = g_bins + ((size_t)b * NBINB + sg * NCB + (l & 7)) * BSTR;
        float4* dst = sbin + sbase[l];
        int n = scnt[l];
#pragma unroll 4
        for (int p = lane; p < n; p += 32)
            dst[p] = src[p];
    }
    __syncthreads();

    // --- per-pixel query: warp w = substrip w/3 (2 rows) x colgroup w%3 ---
    int sr = wid / 3, cg = wid - 3 * sr;
    int r  = lane >> 4, ccol = lane & 15;
    int i  = t * TROWS + 2 * sr + r;
    int j  = 16 * cg + ccol;
    int c  = j / TROWS;
    int l  = sr * NCB + c;
    int tot = scnt[l];
    const float4* bp = sbin + sbase[l];

    int pmax = tot;
#pragma unroll
    for (int o = 16; o > 0; o >>= 1)
        pmax = max(pmax, __shfl_xor_sync(0xffffffffu, pmax, o));

    float sx = (float)i, sy = (float)j;
    int nsel = 0;
    float f0 = 0.0f, f1 = 0.0f;

    for (int p0 = 0; p0 < pmax; p0 += 8) {
        // unconditional LDS.128 (full MLP); reads stay inside sbin[SPAD]
        float4 q0 = bp[p0 + 0], q1 = bp[p0 + 1], q2 = bp[p0 + 2], q3 = bp[p0 + 3];
        float4 q4 = bp[p0 + 4], q5 = bp[p0 + 5], q6 = bp[p0 + 6], q7 = bp[p0 + 7];
        float d0, d1, d2v, d3, d4, d5, d6, d7;
        { float a = sx - q0.x, bb = sy - q0.y; d0  = fmaf(a, a, bb * bb); }
        { float a = sx - q1.x, bb = sy - q1.y; d1  = fmaf(a, a, bb * bb); }
        { float a = sx - q2.x, bb = sy - q2.y; d2v = fmaf(a, a, bb * bb); }
        { float a = sx - q3.x, bb = sy - q3.y; d3  = fmaf(a, a, bb * bb); }
        { float a = sx - q4.x, bb = sy - q4.y; d4  = fmaf(a, a, bb * bb); }
        { float a = sx - q5.x, bb = sy - q5.y; d5  = fmaf(a, a, bb * bb); }
        { float a = sx - q6.x, bb = sy - q6.y; d6  = fmaf(a, a, bb * bb); }
        { float a = sx - q7.x, bb = sy - q7.y; d7  = fmaf(a, a, bb * bb); }
        // ALU-side index guard keeps selection exact (first 16 in index order)
        if (p0 + 0 < tot && d0  < 4.0f && nsel < 16) { f0 += q0.z; f1 += q0.w; nsel++; }
        if (p0 + 1 < tot && d1  < 4.0f && nsel < 16) { f0 += q1.z; f1 += q1.w; nsel++; }
        if (p0 + 2 < tot && d2v < 4.0f && nsel < 16) { f0 += q2.z; f1 += q2.w; nsel++; }
        if (p0 + 3 < tot && d3  < 4.0f && nsel < 16) { f0 += q3.z; f1 += q3.w; nsel++; }
        if (p0 + 4 < tot && d4  < 4.0f && nsel < 16) { f0 += q4.z; f1 += q4.w; nsel++; }
        if (p0 + 5 < tot && d5  < 4.0f && nsel < 16) { f0 += q5.z; f1 += q5.w; nsel++; }
        if (p0 + 6 < tot && d6  < 4.0f && nsel < 16) { f0 += q6.z; f1 += q6.w; nsel++; }
        if (p0 + 7 < tot && d7  < 4.0f && nsel < 16) { f0 += q7.z; f1 += q7.w; nsel++; }
        if (__all_sync(0xffffffffu, (p0 + 8 >= tot) | (nsel >= 16))) break;
    }

    float occ = fmaxf((float)nsel, 1.0f);
    float a0 = __fdiv_rn(f0, occ);
    float a1 = __fdiv_rn(f1, occ);
    float mxv = fmaxf(a0, a1);
    float e0 = expf(a0 - mxv);
    float e1 = expf(a1 - mxv);
    float s  = e0 + e1;
    float nf0 = __fdiv_rn(e0, s);
    float nf1 = __fdiv_rn(e1, s);
    float v = (nf0 == nf1) ? 0.0f : nf1 * 255.0f;

    int base = (b * 3) * SPIX + i * RESV + j;
    out[base]            = v;
    out[base + SPIX]     = v;
    out[base + 2 * SPIX] = v;
}

extern "C" void kernel_launch(void* const* d_in, const int* in_sizes, int n_in,
                              void* d_out, int out_size)
{
    const float* xyz   = (const float*)d_in[0];
    const float* feats = (const float*)d_in[1];
    const float* theta = (const float*)d_in[n_in - 2];
    const float* phi   = (const float*)d_in[n_in - 1];
    float* out = (float*)d_out;

    prep_kernel<<<BTOT, 1024>>>(xyz, feats, theta, phi);
    mask_kernel<<<dim3(TILES, BTOT), 288>>>(out);
}

// round 11
// speedup vs baseline: 1.3950x; 1.2426x over previous
#include <cuda_runtime.h>

#define NPTS  1024
#define BTOT  32
#define RESV  48
#define SPIX  (RESV*RESV)

#define NSUBL 12             // local 2-row sub-strips per block (half batch)
#define NCB   8              // col bins (6 cols each)
#define NBINL 96             // bins per block
#define SCAP  6912           // packed capacity: <=6 copies/pt*1024 + 96*7 pad
#define SPAD  (SCAP+8)

// dynamic smem layout (bytes)
#define OFF_SBIN  0                       // float4 sbin[SPAD]      110720
#define OFF_WBASE 110720                  // int wbase[96][32]       12288
#define OFF_BALS  123008                  // uint balS[32][12]        1536
#define OFF_BALC  124544                  // uint balC[32][8]         1024
#define OFF_PBASE 125568                  // int pbase[96]             384
#define OFF_SCNT  125952                  // int scnt[96]              384
#define OFF_RED   126336                  // float red[128]            512
#define SMEMB     126848

extern __shared__ char smem_raw[];

__device__ __forceinline__ bool sub_cond(float X, int s) {
    // sub-strip s covers rows 2s, 2s+1; reachable iff X in (2s-2, 2s+3)
    return (X > (float)(2 * s) - 2.0f) && (X < (float)(2 * s) + 3.0f);
}
__device__ __forceinline__ bool col_cond(float Y, int c) {
    return (Y > (float)(6 * c) - 2.0f) && (Y < (float)(6 * c + 5) + 2.0f);
}

// ---------------------------------------------------------------------------
// Single fused kernel: 64 blocks x 1024 threads.
// Block b2: batch b = b2>>1, half h = b2&1 (rows 24h .. 24h+23).
// ---------------------------------------------------------------------------
__global__ void __launch_bounds__(1024)
p2m_kernel(const float* __restrict__ xyz,
           const float* __restrict__ feats,
           const float* __restrict__ theta,
           const float* __restrict__ phi,
           float* __restrict__ out)
{
    float4*   sbin  = (float4*)(smem_raw + OFF_SBIN);
    int*      wbase = (int*)(smem_raw + OFF_WBASE);
    unsigned* balS  = (unsigned*)(smem_raw + OFF_BALS);
    unsigned* balC  = (unsigned*)(smem_raw + OFF_BALC);
    int*      pbase = (int*)(smem_raw + OFF_PBASE);
    int*      scnt  = (int*)(smem_raw + OFF_SCNT);
    float*    red   = (float*)(smem_raw + OFF_RED);

    int b2 = blockIdx.x;
    int b = b2 >> 1, h = b2 & 1;
    int k = b >> 2, m = b & 3;
    int tid = threadIdx.x, lane = tid & 31, wid = tid >> 5;

    // ---- Phase A: projection + top-2 features (1 point/thread) ----
    float th = theta[m], ph = phi[m];
    float st = sinf(th), ct = cosf(th);
    float sp = sinf(ph), cp = cosf(ph);
    float U0 = -st, U1 = ct;
    float V0 = ct * sp, V1 = st * sp, V2 = cp;
    float cx = ct * cp, cy = st * cp, cz = sp;

    int g = k * NPTS + tid;
    float x = xyz[3 * g + 0];
    float y = xyz[3 * g + 1];
    float z = xyz[3 * g + 2];
    float dx = x - cx, dy = y - cy, dz = z - cz;
    float c0 = dx * U0 + dy * U1;
    float c1 = dx * V0 + dy * V1 + dz * V2;

    const float4* fr = (const float4*)(feats + (size_t)g * 20);
    float t1 = -1e30f, t2 = -1e30f;
#pragma unroll
    for (int q = 0; q < 5; q++) {
        float4 v = fr[q];
        float f;
        f = v.x; if (f > t1) { t2 = t1; t1 = f; } else if (f > t2) t2 = f;
        f = v.y; if (f > t1) { t2 = t1; t1 = f; } else if (f > t2) t2 = f;
        f = v.z; if (f > t1) { t2 = t1; t1 = f; } else if (f > t2) t2 = f;
        f = v.w; if (f > t1) { t2 = t1; t1 = f; } else if (f > t2) t2 = f;
    }

    // ---- Phase B: exact block minmax over the full batch ----
    float mn0 = c0, mx0 = c0, mn1 = c1, mx1 = c1;
#pragma unroll
    for (int o = 16; o > 0; o >>= 1) {
        mn0 = fminf(mn0, __shfl_xor_sync(0xffffffffu, mn0, o));
        mx0 = fmaxf(mx0, __shfl_xor_sync(0xffffffffu, mx0, o));
        mn1 = fminf(mn1, __shfl_xor_sync(0xffffffffu, mn1, o));
        mx1 = fmaxf(mx1, __shfl_xor_sync(0xffffffffu, mx1, o));
    }
    if (lane == 0) {
        red[wid] = mn0; red[32 + wid] = mx0;
        red[64 + wid] = mn1; red[96 + wid] = mx1;
    }
    __syncthreads();
    mn0 = red[0]; mx0 = red[32]; mn1 = red[64]; mx1 = red[96];
#pragma unroll
    for (int w = 1; w < 32; w++) {
        mn0 = fminf(mn0, red[w]);      mx0 = fmaxf(mx0, red[32 + w]);
        mn1 = fminf(mn1, red[64 + w]); mx1 = fmaxf(mx1, red[96 + w]);
    }
    float ctr0 = (mx0 + mn0) * 0.5f;
    float ctr1 = (mx1 + mn1) * 0.5f;
    float sc0  = fmaxf(mx0 - mn0, 1e-5f) * 0.5f;
    float sc1  = fmaxf(mx1 - mn1, 1e-5f) * 0.5f;

    float X = (__fdiv_rn(c0 - ctr0, sc0) + 1.0f) * 19.2f + 4.8f;
    float Y = (__fdiv_rn(c1 - ctr1, sc1) + 1.0f) * 19.2f + 4.8f;

    // ---- Phase C: factored ballots for this half's 12 substrips + 8 cols ----
#pragma unroll
    for (int sl = 0; sl < NSUBL; sl++) {
        unsigned ba = __ballot_sync(0xffffffffu, sub_cond(X, 12 * h + sl));
        if (lane == 0) balS[wid * NSUBL + sl] = ba;
    }
#pragma unroll
    for (int c = 0; c < NCB; c++) {
        unsigned ba = __ballot_sync(0xffffffffu, col_cond(Y, c));
        if (lane == 0) balC[wid * NCB + c] = ba;
    }
    __syncthreads();

    // ---- Phase D: 96 per-bin cross-warp scans (warp w: bins 3w..3w+2) ----
#pragma unroll
    for (int e = 0; e < 3; e++) {
        int bin = wid * 3 + e;
        int sl = bin >> 3, c = bin & 7;
        int v = __popc(balS[lane * NSUBL + sl] & balC[lane * NCB + c]);
        int incl = v;
#pragma unroll
        for (int o = 1; o < 32; o <<= 1) {
            int n = __shfl_up_sync(0xffffffffu, incl, o);
            if (lane >= o) incl += n;
        }
        wbase[bin * 32 + lane] = incl - v;
        if (lane == 31) pbase[bin] = incl;    // bin total (temp)
    }
    __syncthreads();

    // ---- Phase E: packed-offset scan over 96 bins (warp 0, pad to 8) ----
    if (wid == 0) {
        int carry = 0;
#pragma unroll
        for (int rr = 0; rr < 3; rr++) {
            int lb  = rr * 32 + lane;
            int tot = pbase[lb];
            int pad8 = (tot + 7) & ~7;
            int incl = pad8;
#pragma unroll
            for (int o = 1; o < 32; o <<= 1) {
                int n = __shfl_up_sync(0xffffffffu, incl, o);
                if (lane >= o) incl += n;
            }
            int base = carry + incl - pad8;
            scnt[lb]  = min(tot, max(0, SCAP - base));   // clamp never fires (SCAP bound-proof)
            pbase[lb] = base;
            carry += __shfl_sync(0xffffffffu, incl, 31);
        }
    }
    __syncthreads();

    // ---- Phase F: ordered scatter into packed bins (<=6 copies/point) ----
    {
        unsigned lmask = (1u << lane) - 1u;
        float4 rec = make_float4(X, Y, t2, t1);
        int s0 = (int)floorf((X - 3.0f) * 0.5f);
        if (s0 < 12 * h) s0 = 12 * h;
        int cb0 = (int)floorf((Y - 7.0f) * (1.0f / 6.0f));
        if (cb0 < 0) cb0 = 0;
#pragma unroll
        for (int ds = 0; ds < 4; ds++) {
            int s = s0 + ds;
            if (s >= 12 * h + NSUBL || !sub_cond(X, s)) continue;
            int sl = s - 12 * h;
            unsigned mS = balS[wid * NSUBL + sl];
#pragma unroll
            for (int dc = 0; dc < 3; dc++) {
                int c = cb0 + dc;
                if (c >= NCB || !col_cond(Y, c)) continue;
                unsigned ba = mS & balC[wid * NCB + c];
                int lb = sl * NCB + c;
                int rank = wbase[lb * 32 + wid] + __popc(ba & lmask);
                if (rank < scnt[lb]) sbin[pbase[lb] + rank] = rec;
            }
        }
    }
    __syncthreads();

    // ---- Phase G: per-pixel ball query. 36 warp-tasks, 32 pixels each ----
    for (int task = wid; task < 36; task += 32) {
        int sl = task / 3, cgrp = task - 3 * sl;
        int r  = lane >> 4, ccol = lane & 15;
        int i  = 24 * h + 2 * sl + r;
        int j  = 16 * cgrp + ccol;
        int c  = j / 6;
        int lb = sl * NCB + c;
        int tot = scnt[lb];
        const float4* bp = sbin + pbase[lb];

        int pmax = tot;
#pragma unroll
        for (int o = 16; o > 0; o >>= 1)
            pmax = max(pmax, __shfl_xor_sync(0xffffffffu, pmax, o));

        float sx = (float)i, sy = (float)j;
        int nsel = 0;
        float f0 = 0.0f, f1 = 0.0f;

        for (int p0 = 0; p0 < pmax; p0 += 8) {
            // unconditional LDS.128 (full MLP); reads stay inside sbin[SPAD]
            float4 q0 = bp[p0 + 0], q1 = bp[p0 + 1], q2 = bp[p0 + 2], q3 = bp[p0 + 3];
            float4 q4 = bp[p0 + 4], q5 = bp[p0 + 5], q6 = bp[p0 + 6], q7 = bp[p0 + 7];
            float d0, d1, d2v, d3, d4, d5, d6, d7;
            { float a = sx - q0.x, bb = sy - q0.y; d0  = fmaf(a, a, bb * bb); }
            { float a = sx - q1.x, bb = sy - q1.y; d1  = fmaf(a, a, bb * bb); }
            { float a = sx - q2.x, bb = sy - q2.y; d2v = fmaf(a, a, bb * bb); }
            { float a = sx - q3.x, bb = sy - q3.y; d3  = fmaf(a, a, bb * bb); }
            { float a = sx - q4.x, bb = sy - q4.y; d4  = fmaf(a, a, bb * bb); }
            { float a = sx - q5.x, bb = sy - q5.y; d5  = fmaf(a, a, bb * bb); }
            { float a = sx - q6.x, bb = sy - q6.y; d6  = fmaf(a, a, bb * bb); }
            { float a = sx - q7.x, bb = sy - q7.y; d7  = fmaf(a, a, bb * bb); }
            // ALU-side index guard keeps first-16-in-index-order exact
            if (p0 + 0 < tot && d0  < 4.0f && nsel < 16) { f0 += q0.z; f1 += q0.w; nsel++; }
            if (p0 + 1 < tot && d1  < 4.0f && nsel < 16) { f0 += q1.z; f1 += q1.w; nsel++; }
            if (p0 + 2 < tot && d2v < 4.0f && nsel < 16) { f0 += q2.z; f1 += q2.w; nsel++; }
            if (p0 + 3 < tot && d3  < 4.0f && nsel < 16) { f0 += q3.z; f1 += q3.w; nsel++; }
            if (p0 + 4 < tot && d4  < 4.0f && nsel < 16) { f0 += q4.z; f1 += q4.w; nsel++; }
            if (p0 + 5 < tot && d5  < 4.0f && nsel < 16) { f0 += q5.z; f1 += q5.w; nsel++; }
            if (p0 + 6 < tot && d6  < 4.0f && nsel < 16) { f0 += q6.z; f1 += q6.w; nsel++; }
            if (p0 + 7 < tot && d7  < 4.0f && nsel < 16) { f0 += q7.z; f1 += q7.w; nsel++; }
            if (__all_sync(0xffffffffu, (p0 + 8 >= tot) | (nsel >= 16))) break;
        }

        float occ = fmaxf((float)nsel, 1.0f);
        float a0 = __fdiv_rn(f0, occ);
        float a1 = __fdiv_rn(f1, occ);
        float mxv = fmaxf(a0, a1);
        float e0 = expf(a0 - mxv);
        float e1 = expf(a1 - mxv);
        float ssum = e0 + e1;
        float nf0 = __fdiv_rn(e0, ssum);
        float nf1 = __fdiv_rn(e1, ssum);
        float v = (nf0 == nf1) ? 0.0f : nf1 * 255.0f;

        int base = (b * 3) * SPIX + i * RESV + j;
        out[base]            = v;
        out[base + SPIX]     = v;
        out[base + 2 * SPIX] = v;
    }
}

extern "C" void kernel_launch(void* const* d_in, const int* in_sizes, int n_in,
                              void* d_out, int out_size)
{
    const float* xyz   = (const float*)d_in[0];
    const float* feats = (const float*)d_in[1];
    const float* theta = (const float*)d_in[n_in - 2];
    const float* phi   = (const float*)d_in[n_in - 1];
    float* out = (float*)d_out;

    cudaFuncSetAttribute(p2m_kernel,
                         cudaFuncAttributeMaxDynamicSharedMemorySize, SMEMB);
    p2m_kernel<<<BTOT * 2, 1024, SMEMB>>>(xyz, feats, theta, phi, out);
}